// round 2
// baseline (speedup 1.0000x reference)
#include <cuda_runtime.h>
#include <cuda_bf16.h>
#include <cstdint>

#define B_ 128
#define T_ 4096
#define F_ 64
#define H_ 128
#define G_ 512   /* 4*H */

// Scratch: precomputed input gates xg[b][t][512] = X[b,t,:]@W_ih^T + b_ih + b_hh
// 128*4096*512 floats = 1 GiB. __device__ global = allowed scratch mechanism.
__device__ float g_xg[268435456ull];

// ---------------- f32x2 helpers (sm_103a packed fp32: 2x FFMA throughput) ---
__device__ __forceinline__ unsigned long long packf2(float x, float y) {
    unsigned long long r;
    asm("mov.b64 %0, {%1, %2};" : "=l"(r) : "f"(x), "f"(y));
    return r;
}
__device__ __forceinline__ float2 unpackf2(unsigned long long v) {
    float2 r;
    asm("mov.b64 {%0, %1}, %2;" : "=f"(r.x), "=f"(r.y) : "l"(v));
    return r;
}
__device__ __forceinline__ unsigned long long ffma2(unsigned long long a,
                                                    unsigned long long b,
                                                    unsigned long long c) {
    unsigned long long d;
    asm("fma.rn.f32x2 %0, %1, %2, %3;" : "=l"(d) : "l"(a), "l"(b), "l"(c));
    return d;
}
// bf16x2 (u32) -> f32x2 (u64): lo = u<<16, hi = u & 0xffff0000 (pure ALU pipe)
__device__ __forceinline__ unsigned long long bf2tof2(unsigned int u) {
    unsigned int lo = u << 16;
    unsigned int hi = u & 0xFFFF0000u;
    unsigned long long r;
    asm("mov.b64 %0, {%1, %2};" : "=l"(r) : "r"(lo), "r"(hi));
    return r;
}

__device__ __forceinline__ float sigmoidf_(float x) {
    return __fdividef(1.0f, 1.0f + __expf(-x));
}
__device__ __forceinline__ float tanhf_(float x) {
    float ax = fabsf(x);
    float e  = __expf(-2.0f * ax);           // e in (0,1], never overflows
    float t  = __fdividef(1.0f - e, 1.0f + e);
    return copysignf(t, x);
}

// ---------------------------------------------------------------------------
// Kernel 1: xg[b][t][j] = sum_f X[b][t][f] * W_ih[j][f] + b_ih[j] + b_hh[j]
// grid (T/64, B), 256 threads. Thread handles rows (t, t+256), 64 timesteps.
// ---------------------------------------------------------------------------
__global__ __launch_bounds__(256) void xg_kernel(
    const float* __restrict__ X,
    const float* __restrict__ W_ih,
    const float* __restrict__ b_ih,
    const float* __restrict__ b_hh)
{
    extern __shared__ float smem[];
    float* sW = smem;                 // 512 x 65 (pad 1 -> conflict-free scalar reads)
    float* sX = smem + 512 * 65;      // 64 x 64

    const int t  = threadIdx.x;
    const int b  = blockIdx.y;
    const int t0 = blockIdx.x * 64;

    // Stage W_ih (coalesced global -> padded shared)
    for (int idx = t; idx < 512 * 64; idx += 256) {
        int j = idx >> 6, k = idx & 63;
        sW[j * 65 + k] = W_ih[idx];
    }
    // Stage X chunk
    const float* Xb = X + ((size_t)b * T_ + t0) * F_;
    for (int idx = t; idx < 64 * 64; idx += 256) sX[idx] = Xb[idx];
    __syncthreads();

    const int r0 = t, r1 = t + 256;

    // Per-thread weight rows in registers as f32x2 pairs
    unsigned long long wpA[32], wpB[32];
#pragma unroll
    for (int p = 0; p < 32; ++p) {
        wpA[p] = packf2(sW[r0 * 65 + 2 * p], sW[r0 * 65 + 2 * p + 1]);
        wpB[p] = packf2(sW[r1 * 65 + 2 * p], sW[r1 * 65 + 2 * p + 1]);
    }
    const float biasA = __ldg(b_ih + r0) + __ldg(b_hh + r0);
    const float biasB = __ldg(b_ih + r1) + __ldg(b_hh + r1);

    float* outb = g_xg + ((size_t)b * T_ + t0) * G_;

    for (int tt = 0; tt < 64; ++tt) {
        const float4* x4 = (const float4*)(sX + tt * 64);
        unsigned long long aA0 = 0, aA1 = 0, aB0 = 0, aB1 = 0;
#pragma unroll
        for (int q = 0; q < 16; ++q) {
            float4 v = x4[q];   // broadcast read
            unsigned long long h01 = packf2(v.x, v.y);
            unsigned long long h23 = packf2(v.z, v.w);
            aA0 = ffma2(wpA[2 * q],     h01, aA0);
            aA1 = ffma2(wpA[2 * q + 1], h23, aA1);
            aB0 = ffma2(wpB[2 * q],     h01, aB0);
            aB1 = ffma2(wpB[2 * q + 1], h23, aB1);
        }
        float2 u0 = unpackf2(aA0), u1 = unpackf2(aA1);
        float2 v0 = unpackf2(aB0), v1 = unpackf2(aB1);
        float sA = (u0.x + u0.y) + (u1.x + u1.y) + biasA;
        float sB = (v0.x + v0.y) + (v1.x + v1.y) + biasB;
        outb[(size_t)tt * G_ + r0] = sA;   // coalesced
        outb[(size_t)tt * G_ + r1] = sB;
    }
}

// ---------------------------------------------------------------------------
// Kernel 2: persistent recurrent LSTM. One CTA per batch row, 256 threads.
// Thread t owns gate rows (t, t+256):
//   t <  128: (i_t, g_t)         t >= 128 (j=t-128): (f_j, o_j), owns c_j/h_j
// W_hh rows: k=0..95 in registers (fp32 pairs), k=96..127 streamed from
// shared as bf16 pairs (ALU unpack, off the FMA critical pipe).
// ---------------------------------------------------------------------------
__global__ __launch_bounds__(256, 1) void lstm_kernel(
    const float* __restrict__ W_hh,
    float* __restrict__ out)
{
    __shared__ alignas(16) float sh_h[128];
    __shared__ float sh_ig[128];
    __shared__ uint4 sws[8][256];   // streamed bf16 weight pairs, [vec][thread]

    const int t = threadIdx.x;
    const int b = blockIdx.x;
    const int r0 = t, r1 = t + 256;

    const float* WA = W_hh + (size_t)r0 * H_;
    const float* WB = W_hh + (size_t)r1 * H_;

    // Register-resident weights, k = 0..95 (48 f32x2 pairs per row)
    unsigned long long wpA[48], wpB[48];
#pragma unroll
    for (int q = 0; q < 24; ++q) {
        float4 a = __ldg((const float4*)(WA + 4 * q));
        wpA[2 * q]     = packf2(a.x, a.y);
        wpA[2 * q + 1] = packf2(a.z, a.w);
        float4 c4 = __ldg((const float4*)(WB + 4 * q));
        wpB[2 * q]     = packf2(c4.x, c4.y);
        wpB[2 * q + 1] = packf2(c4.z, c4.w);
    }
    // Streamed weights, k = 96..127, packed bf16x2 into shared
    {
        unsigned int uA[16], uB[16];
#pragma unroll
        for (int p = 0; p < 16; ++p) {
            float a0 = __ldg(WA + 96 + 2 * p), a1 = __ldg(WA + 97 + 2 * p);
            float c0 = __ldg(WB + 96 + 2 * p), c1 = __ldg(WB + 97 + 2 * p);
            unsigned short sa0 = __bfloat16_as_ushort(__float2bfloat16(a0));
            unsigned short sa1 = __bfloat16_as_ushort(__float2bfloat16(a1));
            unsigned short sb0 = __bfloat16_as_ushort(__float2bfloat16(c0));
            unsigned short sb1 = __bfloat16_as_ushort(__float2bfloat16(c1));
            uA[p] = ((unsigned)sa1 << 16) | (unsigned)sa0;
            uB[p] = ((unsigned)sb1 << 16) | (unsigned)sb0;
        }
#pragma unroll
        for (int i = 0; i < 4; ++i) {
            sws[i][t]     = make_uint4(uA[4*i], uA[4*i+1], uA[4*i+2], uA[4*i+3]);
            sws[4 + i][t] = make_uint4(uB[4*i], uB[4*i+1], uB[4*i+2], uB[4*i+3]);
        }
    }
    if (t < 128) sh_h[t] = 0.0f;
    __syncthreads();

    const float* xb = g_xg + (size_t)b * T_ * G_;
    const float* pA = xb + r0;
    const float* pB = xb + r1;
    float xgA = __ldg(pA);
    float xgB = __ldg(pB);

    float c = 0.0f;
    float h_out = 0.0f;
    const float4* h4p = (const float4*)sh_h;

    for (int ts = 0; ts < T_; ++ts) {
        // software prefetch of next step's xg (covers DRAM latency)
        const int inc = (ts < T_ - 1) ? G_ : 0;
        float nxA = __ldg(pA + inc);
        float nxB = __ldg(pB + inc);

        unsigned long long aA0 = 0, aA1 = 0, aB0 = 0, aB1 = 0;
#pragma unroll
        for (int q = 0; q < 24; ++q) {        // k = 0..95, register weights
            float4 v = h4p[q];                 // broadcast LDS.128
            unsigned long long h01 = packf2(v.x, v.y);
            unsigned long long h23 = packf2(v.z, v.w);
            aA0 = ffma2(wpA[2 * q],     h01, aA0);
            aA1 = ffma2(wpA[2 * q + 1], h23, aA1);
            aB0 = ffma2(wpB[2 * q],     h01, aB0);
            aB1 = ffma2(wpB[2 * q + 1], h23, aB1);
        }
#pragma unroll
        for (int i = 0; i < 4; ++i) {         // k = 96..127, streamed bf16
            uint4 ua = sws[i][t];
            uint4 ub = sws[4 + i][t];
            float4 v0 = h4p[24 + 2 * i];
            float4 v1 = h4p[25 + 2 * i];
            unsigned long long h01 = packf2(v0.x, v0.y);
            unsigned long long h23 = packf2(v0.z, v0.w);
            unsigned long long h45 = packf2(v1.x, v1.y);
            unsigned long long h67 = packf2(v1.z, v1.w);
            aA0 = ffma2(bf2tof2(ua.x), h01, aA0);
            aA1 = ffma2(bf2tof2(ua.y), h23, aA1);
            aA0 = ffma2(bf2tof2(ua.z), h45, aA0);
            aA1 = ffma2(bf2tof2(ua.w), h67, aA1);
            aB0 = ffma2(bf2tof2(ub.x), h01, aB0);
            aB1 = ffma2(bf2tof2(ub.y), h23, aB1);
            aB0 = ffma2(bf2tof2(ub.z), h45, aB0);
            aB1 = ffma2(bf2tof2(ub.w), h67, aB1);
        }
        float2 u0 = unpackf2(aA0), u1 = unpackf2(aA1);
        float2 w0 = unpackf2(aB0), w1 = unpackf2(aB1);
        float gA = (u0.x + u0.y) + (u1.x + u1.y) + xgA;
        float gB = (w0.x + w0.y) + (w1.x + w1.y) + xgB;

        float fg = 0.0f, og = 0.0f;
        if (t < 128) {
            sh_ig[t] = sigmoidf_(gA) * tanhf_(gB);   // i * g
        } else {
            fg = sigmoidf_(gA);                       // f
            og = sigmoidf_(gB);                       // o
        }
        __syncthreads();                              // ig visible
        if (t >= 128) {
            c = fg * c + sh_ig[t - 128];
            float h = og * tanhf_(c);
            sh_h[t - 128] = h;
            h_out = h;
        }
        __syncthreads();                              // h visible for next step

        pA += inc; pB += inc;
        xgA = nxA; xgB = nxB;
    }

    if (t >= 128) out[(size_t)b * H_ + (t - 128)] = h_out;
}

// ---------------------------------------------------------------------------
extern "C" void kernel_launch(void* const* d_in, const int* in_sizes, int n_in,
                              void* d_out, int out_size)
{
    const float* X    = (const float*)d_in[0];   // [128,4096,64]
    const float* W_ih = (const float*)d_in[1];   // [512,64]
    const float* W_hh = (const float*)d_in[2];   // [512,128]
    const float* b_ih = (const float*)d_in[3];   // [512]
    const float* b_hh = (const float*)d_in[4];   // [512]
    float* out = (float*)d_out;                  // [128,128]

    size_t smem1 = (size_t)(512 * 65 + 64 * 64) * sizeof(float);  // ~146 KB
    cudaFuncSetAttribute(xg_kernel,
                         cudaFuncAttributeMaxDynamicSharedMemorySize, (int)smem1);

    dim3 g1(T_ / 64, B_);
    xg_kernel<<<g1, 256, smem1>>>(X, W_ih, b_ih, b_hh);
    lstm_kernel<<<B_, 256>>>(W_hh, out);
}